// round 7
// baseline (speedup 1.0000x reference)
#include <cuda_runtime.h>
#include <cuda_fp16.h>

#define IC 1152
#define BB 256
#define NU 10
#define US 16
#define DU 160   /* NU*US */
#define IU 8

// Scratch (allocation-free rule: __device__ globals)
__device__ __align__(16) __half g_Uh[(size_t)IC * BB * DU];  // 94.4 MB fp16 u_hat, layout [c][b][du]
__device__ __align__(16) __half g_Vh[BB * DU];               // v in fp16 for agree pass
__device__ float g_Bij[IC * NU];                             // routing logits

// ---------------------------------------------------------------------------
// k_build: u_hat[c][b][du] = sum_i W[c,du,i] * x[b,i,c], stored fp16.
// grid 1152 (c), block 320 (du = t%160, b-parity = t/160)
// ---------------------------------------------------------------------------
__global__ void __launch_bounds__(320) k_build(const float* __restrict__ x,
                                               const float* __restrict__ W) {
    __shared__ float Wt[IU][DU];     // transposed W[c] for conflict-free LDS
    __shared__ float xs[BB][IU];     // x[:, :, c]
    const int c = blockIdx.x;
    const int t = threadIdx.x;

    // zero routing logits (must happen every launch; done before any reader kernel)
    if (blockIdx.x == 0) {
        for (int i = t; i < IC * NU; i += 320) g_Bij[i] = 0.0f;
    }

    const float* Wc = W + c * (DU * IU);
    for (int idx = t; idx < DU * IU; idx += 320) {
        const int du = idx >> 3, i = idx & 7;
        Wt[i][du] = Wc[idx];
    }
    for (int idx = t; idx < BB * IU; idx += 320) {
        const int b = idx >> 3, i = idx & 7;
        xs[b][i] = x[(b * IU + i) * IC + c];
    }
    __syncthreads();

    const int du = t % DU;
    const int hp = t / DU;  // 0 or 1
    const float w0 = Wt[0][du], w1 = Wt[1][du], w2 = Wt[2][du], w3 = Wt[3][du];
    const float w4 = Wt[4][du], w5 = Wt[5][du], w6 = Wt[6][du], w7 = Wt[7][du];
    __half* out = g_Uh + (size_t)c * (BB * DU) + du;

#pragma unroll 4
    for (int b = hp; b < BB; b += 2) {
        const float4 xa = *reinterpret_cast<const float4*>(&xs[b][0]);
        const float4 xb = *reinterpret_cast<const float4*>(&xs[b][4]);
        float acc = w0 * xa.x + w1 * xa.y + w2 * xa.z + w3 * xa.w
                  + w4 * xb.x + w5 * xb.y + w6 * xb.z + w7 * xb.w;
        out[b * DU] = __float2half_rn(acc);
    }
}

// ---------------------------------------------------------------------------
// k_s: fused (softmax over channels) + s_j reduce + squash -> v
// grid 256 (b), block 320: dug = t%20 (8 du each, within one d), cp = t/20 (16-way c split)
// ---------------------------------------------------------------------------
__global__ void __launch_bounds__(320) k_s(float* __restrict__ vout) {
    __shared__ float pool[IC * NU];          // 46 KB: exp(b_ij - max), later reused as reduce buf
    __shared__ float pm[16][NU], psum[16][NU];
    __shared__ float cmax[NU], cinv[NU];
    __shared__ float svec[DU];
    __shared__ float msq[US];

    const int t = threadIdx.x;
    const int b = blockIdx.x;

    // --- softmax over in_channels (axis 0) of b_ij [IC, NU] ---
    for (int i = t; i < IC * NU; i += 320) pool[i] = g_Bij[i];
    __syncthreads();
    if (t < 160) {
        const int d = t % NU, seg = t / NU;
        float m = -1e30f;
        for (int c = seg; c < IC; c += 16) m = fmaxf(m, pool[c * NU + d]);
        pm[seg][d] = m;
    }
    __syncthreads();
    if (t < NU) {
        float m = pm[0][t];
#pragma unroll
        for (int s = 1; s < 16; s++) m = fmaxf(m, pm[s][t]);
        cmax[t] = m;
    }
    __syncthreads();
    for (int i = t; i < IC * NU; i += 320) pool[i] = __expf(pool[i] - cmax[i % NU]);
    __syncthreads();
    if (t < 160) {
        const int d = t % NU, seg = t / NU;
        float s = 0.0f;
        for (int c = seg; c < IC; c += 16) s += pool[c * NU + d];
        psum[seg][d] = s;
    }
    __syncthreads();
    if (t < NU) {
        float s = 0.0f;
#pragma unroll
        for (int k = 0; k < 16; k++) s += psum[k][t];
        cinv[t] = 1.0f / s;
    }
    __syncthreads();

    // --- s_j[b,du] = sum_c c_ij[c,d] * u_hat[c][b][du] ---
    const int dug = t % 20, cp = t / 20;
    const int du0 = dug * 8;
    const int d = du0 / US;           // each 8-du group lies in one d
    const float inv = cinv[d];
    float acc[8];
#pragma unroll
    for (int j = 0; j < 8; j++) acc[j] = 0.0f;

    const __half* Ub = g_Uh + b * DU + du0;
#pragma unroll 4
    for (int k = 0; k < 72; k++) {
        const int c = cp + (k << 4);
        const uint4 raw = *reinterpret_cast<const uint4*>(Ub + (size_t)c * (BB * DU));
        const float w = pool[c * NU + d] * inv;
        const __half2* h = reinterpret_cast<const __half2*>(&raw);
#pragma unroll
        for (int j = 0; j < 4; j++) {
            const float2 f = __half22float2(h[j]);
            acc[2 * j]     += w * f.x;
            acc[2 * j + 1] += w * f.y;
        }
    }
    __syncthreads();  // pool (exp values) fully consumed; reuse as reduce buffer
    float* red = pool;
#pragma unroll
    for (int j = 0; j < 8; j++) red[cp * DU + du0 + j] = acc[j];
    __syncthreads();
    if (t < DU) {
        float s = 0.0f;
#pragma unroll
        for (int p = 0; p < 16; p++) s += red[p * DU + t];
        svec[t] = s;
    }
    __syncthreads();

    // --- squash: norm over num_units axis per (b, u) ---
    if (t < US) {
        float m = 0.0f;
#pragma unroll
        for (int dd = 0; dd < NU; dd++) {
            const float v = svec[dd * US + t];
            m += v * v;
        }
        msq[t] = m;
    }
    __syncthreads();
    if (t < DU) {
        const float m = msq[t % US];
        const float scale = sqrtf(m) / (1.0f + m);
        const float v = svec[t] * scale;
        vout[b * DU + t] = v;
        g_Vh[b * DU + t] = __float2half_rn(v);
    }
}

// ---------------------------------------------------------------------------
// k_agree: b_ij[c,d] += (1/B) sum_{b,u} u_hat[c][b][d*16+u] * v[b][d*16+u]
// grid 144 (8 c's per block), block 320: dug = t%20, bp = t/20
// ---------------------------------------------------------------------------
__global__ void __launch_bounds__(320) k_agree() {
    __shared__ float sacc[320];
    const int t = threadIdx.x;
    const int dug = t % 20, bp = t / 20;   // bp in [0,16)
    const int du0 = dug * 8;
    const int c0 = blockIdx.x * 8;

    for (int ci = 0; ci < 8; ci++) {
        const int c = c0 + ci;
        const __half* Ub = g_Uh + (size_t)c * (BB * DU) + du0;
        float acc = 0.0f;
#pragma unroll 4
        for (int bs = 0; bs < 16; bs++) {
            const int b = bs * 16 + bp;
            const uint4 ur = *reinterpret_cast<const uint4*>(Ub + b * DU);
            const uint4 vr = *reinterpret_cast<const uint4*>(g_Vh + b * DU + du0);
            const __half2* up = reinterpret_cast<const __half2*>(&ur);
            const __half2* vp = reinterpret_cast<const __half2*>(&vr);
#pragma unroll
            for (int j = 0; j < 4; j++) {
                const float2 uf = __half22float2(up[j]);
                const float2 vf = __half22float2(vp[j]);
                acc += uf.x * vf.x + uf.y * vf.y;
            }
        }
        sacc[t] = acc;
        __syncthreads();
        if (t < NU) {
            float s = 0.0f;
#pragma unroll
            for (int p = 0; p < 16; p++)
                s += sacc[p * 20 + 2 * t] + sacc[p * 20 + 2 * t + 1];
            g_Bij[c * NU + t] += s * (1.0f / 256.0f);
        }
        __syncthreads();
    }
}

// ---------------------------------------------------------------------------
extern "C" void kernel_launch(void* const* d_in, const int* in_sizes, int n_in,
                              void* d_out, int out_size) {
    const float* x;
    const float* W;
    // identify by element count: x = 256*8*1152 = 2359296, W = 1152*10*16*8 = 1474560
    if (in_sizes[0] == BB * IU * IC) {
        x = (const float*)d_in[0];
        W = (const float*)d_in[1];
    } else {
        W = (const float*)d_in[0];
        x = (const float*)d_in[1];
    }
    float* out = (float*)d_out;

    k_build<<<IC, 320>>>(x, W);
    for (int it = 0; it < 3; it++) {
        k_s<<<BB, 320>>>(out);
        if (it < 2) k_agree<<<144, 320>>>();
    }
}

// round 8
// speedup vs baseline: 2.3297x; 2.3297x over previous
#include <cuda_runtime.h>
#include <cuda_fp16.h>
#include <cstdint>

#define IC 1152
#define BB 256
#define NU 10
#define US 16
#define DU 160   /* NU*US */
#define IU 8
#define KK (IC*IU)   /* 9216 */
#define KS 72        /* k-split for s-GEMM: chunk = 9216/72 = 128 */

#define SA 24    // As smem stride (halfs) — pad to kill ldmatrix conflicts
#define SB 168   // Bs smem stride (halfs)

// ---- scratch (__device__ globals per allocation rules) ----
__device__ __align__(16) __half g_Xh [(size_t)BB * KK];   // [b][c*8+i]  4.7MB
__device__ __align__(16) __half g_XhT[(size_t)KK * BB];   // [c*8+i][b]  4.7MB
__device__ __align__(16) __half g_Wt [(size_t)KK * DU];   // [c*8+i][du] 2.9MB
__device__ __align__(16) __half g_Vh [BB * DU];           // v fp16
__device__ __align__(16) float  g_Sp [(size_t)KS * BB * DU]; // s partials 11.8MB
__device__ float g_Bij[IC * NU];
__device__ float g_Cij[IC * NU];

// ---------------------------------------------------------------------------
// PTX helpers
// ---------------------------------------------------------------------------
__device__ __forceinline__ uint32_t smem_u32(const void* p) {
    return (uint32_t)__cvta_generic_to_shared(p);
}
__device__ __forceinline__ void ldsm_x4(uint32_t& a0, uint32_t& a1, uint32_t& a2,
                                        uint32_t& a3, uint32_t addr) {
    asm volatile("ldmatrix.sync.aligned.m8n8.x4.shared.b16 {%0,%1,%2,%3}, [%4];"
                 : "=r"(a0), "=r"(a1), "=r"(a2), "=r"(a3) : "r"(addr));
}
__device__ __forceinline__ void ldsm_x2t(uint32_t& b0, uint32_t& b1, uint32_t addr) {
    asm volatile("ldmatrix.sync.aligned.m8n8.x2.trans.shared.b16 {%0,%1}, [%2];"
                 : "=r"(b0), "=r"(b1) : "r"(addr));
}
__device__ __forceinline__ void mma16816(float& c0, float& c1, float& c2, float& c3,
                                         uint32_t a0, uint32_t a1, uint32_t a2, uint32_t a3,
                                         uint32_t b0, uint32_t b1) {
    asm volatile("mma.sync.aligned.m16n8k16.row.col.f32.f16.f16.f32 "
                 "{%0,%1,%2,%3}, {%4,%5,%6,%7}, {%8,%9}, {%0,%1,%2,%3};"
                 : "+f"(c0), "+f"(c1), "+f"(c2), "+f"(c3)
                 : "r"(a0), "r"(a1), "r"(a2), "r"(a3), "r"(b0), "r"(b1));
}

// ---------------------------------------------------------------------------
// prep: Xh[b][c*8+i] = fp16(x[b,i,c]); coalesced reads over c, uint4 stores.
// ---------------------------------------------------------------------------
__global__ void __launch_bounds__(288) k_prep_xh(const float* __restrict__ x) {
    const int b = blockIdx.x;
    for (int c = threadIdx.x; c < IC; c += 288) {
        __half h[8];
#pragma unroll
        for (int i = 0; i < 8; i++)
            h[i] = __float2half_rn(x[(b * IU + i) * IC + c]);
        *reinterpret_cast<uint4*>(&g_Xh[(size_t)b * KK + c * 8]) =
            *reinterpret_cast<uint4*>(h);
    }
}

// prep: XhT[ci][b] via smem transpose of 64x64 tiles of Xh
__global__ void __launch_bounds__(256) k_prep_xt() {
    __shared__ __half s[64][72];
    const int ci0 = blockIdx.x * 64, b0 = blockIdx.y * 64;
    const int t = threadIdx.x;
#pragma unroll
    for (int it = 0; it < 2; it++) {
        const int idx = t + it * 256;
        const int bl = idx >> 3, cv = idx & 7;
        uint4 raw = *reinterpret_cast<const uint4*>(
            &g_Xh[(size_t)(b0 + bl) * KK + ci0 + cv * 8]);
        const __half* h = reinterpret_cast<const __half*>(&raw);
#pragma unroll
        for (int j = 0; j < 8; j++) s[cv * 8 + j][bl] = h[j];
    }
    __syncthreads();
#pragma unroll
    for (int it = 0; it < 2; it++) {
        const int idx = t + it * 256;
        const int cl = idx >> 3, bv = idx & 7;
        *reinterpret_cast<uint4*>(&g_XhT[(size_t)(ci0 + cl) * BB + b0 + bv * 8]) =
            *reinterpret_cast<const uint4*>(&s[cl][bv * 8]);
    }
}

// prep: Wt[c*8+i][du] = fp16(W[c][du][i]); also zero b_ij
__global__ void __launch_bounds__(160) k_prep_wt(const float* __restrict__ W) {
    __shared__ __half sw[8][168];
    const int c = blockIdx.x, t = threadIdx.x;  // t = du
    if (c == 0) {
        for (int i = t; i < IC * NU; i += 160) g_Bij[i] = 0.0f;
    }
    const float4* wp = reinterpret_cast<const float4*>(&W[(c * DU + t) * IU]);
    const float4 w0 = wp[0], w1 = wp[1];
    sw[0][t] = __float2half_rn(w0.x); sw[1][t] = __float2half_rn(w0.y);
    sw[2][t] = __float2half_rn(w0.z); sw[3][t] = __float2half_rn(w0.w);
    sw[4][t] = __float2half_rn(w1.x); sw[5][t] = __float2half_rn(w1.y);
    sw[6][t] = __float2half_rn(w1.z); sw[7][t] = __float2half_rn(w1.w);
    __syncthreads();
    const int i = t / 20, v = (t % 20) * 8;
    *reinterpret_cast<uint4*>(&g_Wt[(size_t)(c * 8 + i) * DU + v]) =
        *reinterpret_cast<const uint4*>(&sw[i][v]);
}

// ---------------------------------------------------------------------------
// softmax over channels: c_ij[c,d] = softmax_c(b_ij[:,d]). grid 10, block 128
// ---------------------------------------------------------------------------
__global__ void __launch_bounds__(128) k_softmax() {
    __shared__ float red[128];
    const int d = blockIdx.x, t = threadIdx.x;
    float m = -1e30f;
    for (int c = t; c < IC; c += 128) m = fmaxf(m, g_Bij[c * NU + d]);
    red[t] = m; __syncthreads();
    for (int o = 64; o > 0; o >>= 1) {
        if (t < o) red[t] = fmaxf(red[t], red[t + o]);
        __syncthreads();
    }
    const float mx = red[0];
    __syncthreads();
    float s = 0.0f;
    for (int c = t; c < IC; c += 128) s += __expf(g_Bij[c * NU + d] - mx);
    red[t] = s; __syncthreads();
    for (int o = 64; o > 0; o >>= 1) {
        if (t < o) red[t] += red[t + o];
        __syncthreads();
    }
    const float inv = 1.0f / red[0];
    for (int c = t; c < IC; c += 128)
        g_Cij[c * NU + d] = __expf(g_Bij[c * NU + d] - mx) * inv;
}

// ---------------------------------------------------------------------------
// s-GEMM: Sp[ks] += Xh[M=256,K=9216] @ (Wt * cij)[K,N=160], split-K.
// grid (KS=72, mtiles=4), block 256 = 8 warps (4 m x 2 n), BM=64, Kchunk=128.
// ---------------------------------------------------------------------------
__global__ void __launch_bounds__(256) k_sgemm() {
    __shared__ __half As[64 * SA];
    __shared__ __half Bs[16 * SB];
    const int ks = blockIdx.x, mt = blockIdx.y;
    const int m0 = mt * 64, k0 = ks * 128;
    const int t = threadIdx.x, lane = t & 31, w = t >> 5;
    const int wm = w & 3, wn = w >> 2;

    float acc[10][4];
#pragma unroll
    for (int i = 0; i < 10; i++)
#pragma unroll
        for (int j = 0; j < 4; j++) acc[i][j] = 0.0f;

    const uint32_t aaddr =
        smem_u32(&As[(wm * 16 + (lane & 15)) * SA + ((lane >> 4) << 3)]);
    const uint32_t baddr0 = smem_u32(&Bs[(lane & 15) * SB + wn * 80]);

    for (int kk = 0; kk < 8; kk++) {
        const int kg = k0 + kk * 16;
        // stage A: 64 x 16 halfs
        if (t < 128) {
            const int r = t >> 1, p = t & 1;
            *reinterpret_cast<uint4*>(&As[r * SA + p * 8]) =
                *reinterpret_cast<const uint4*>(&g_Xh[(size_t)(m0 + r) * KK + kg + p * 8]);
        }
        // stage B: 16 x 160 halfs, scaled by cij[c][d]
        for (int idx = t; idx < 320; idx += 256) {
            const int kr = idx / 20, n8 = (idx % 20) * 8;
            const int c = (kg + kr) >> 3, d = n8 >> 4;
            const __half2 s2 = __float2half2_rn(g_Cij[c * NU + d]);
            uint4 raw = *reinterpret_cast<const uint4*>(&g_Wt[(size_t)(kg + kr) * DU + n8]);
            __half2* h = reinterpret_cast<__half2*>(&raw);
#pragma unroll
            for (int j = 0; j < 4; j++) h[j] = __hmul2(h[j], s2);
            *reinterpret_cast<uint4*>(&Bs[kr * SB + n8]) = raw;
        }
        __syncthreads();
        uint32_t a0, a1, a2, a3;
        ldsm_x4(a0, a1, a2, a3, aaddr);
#pragma unroll
        for (int nt = 0; nt < 10; nt++) {
            uint32_t b0, b1;
            ldsm_x2t(b0, b1, baddr0 + nt * 16);  // 8 halfs = 16 bytes
            mma16816(acc[nt][0], acc[nt][1], acc[nt][2], acc[nt][3],
                     a0, a1, a2, a3, b0, b1);
        }
        __syncthreads();
    }
    // epilogue: write partials
    const int rg = lane >> 2, cb = (lane & 3) * 2;
    const int m = m0 + wm * 16 + rg;
#pragma unroll
    for (int nt = 0; nt < 10; nt++) {
        const int n = wn * 80 + nt * 8 + cb;
        float2 lo = make_float2(acc[nt][0], acc[nt][1]);
        float2 hi = make_float2(acc[nt][2], acc[nt][3]);
        *reinterpret_cast<float2*>(&g_Sp[((size_t)ks * BB + m) * DU + n]) = lo;
        *reinterpret_cast<float2*>(&g_Sp[((size_t)ks * BB + m + 8) * DU + n]) = hi;
    }
}

// ---------------------------------------------------------------------------
// squash: sum split-K partials, squash over num_units, write vout + Vh
// grid 256 (b), block 160 (du)
// ---------------------------------------------------------------------------
__global__ void __launch_bounds__(160) k_squash(float* __restrict__ vout) {
    __shared__ float sv[DU];
    __shared__ float msq[US];
    const int b = blockIdx.x, t = threadIdx.x;
    float s = 0.0f;
#pragma unroll 8
    for (int ks = 0; ks < KS; ks++)
        s += g_Sp[((size_t)ks * BB + b) * DU + t];
    sv[t] = s;
    __syncthreads();
    if (t < US) {
        float m = 0.0f;
#pragma unroll
        for (int d = 0; d < NU; d++) {
            const float v = sv[d * US + t];
            m += v * v;
        }
        msq[t] = m;
    }
    __syncthreads();
    const float m = msq[t & 15];
    const float scale = sqrtf(m) / (1.0f + m);
    const float v = s * scale;
    vout[b * DU + t] = v;
    g_Vh[b * DU + t] = __float2half_rn(v);
}

// ---------------------------------------------------------------------------
// agree-GEMM with fused W-dot epilogue:
//   acc[ci,du] = sum_b XhT[ci,b] * Vh[b,du];  b_ij[c,d] += (1/B) sum_{i,u} Wt*acc
// grid (72 mtiles of 128 rows, 2 n-halves of 80), block 256 = 8 warps (m16 each)
// ---------------------------------------------------------------------------
__global__ void __launch_bounds__(256) k_agree() {
    __shared__ __half As[128 * SA];
    __shared__ __half Bs[16 * SB];
    const int mt = blockIdx.x, nb = blockIdx.y;
    const int m0 = mt * 128, n0 = nb * 80;
    const int t = threadIdx.x, lane = t & 31, w = t >> 5;

    float acc[10][4];
#pragma unroll
    for (int i = 0; i < 10; i++)
#pragma unroll
        for (int j = 0; j < 4; j++) acc[i][j] = 0.0f;

    const uint32_t aaddr =
        smem_u32(&As[(w * 16 + (lane & 15)) * SA + ((lane >> 4) << 3)]);
    const uint32_t baddr0 = smem_u32(&Bs[(lane & 15) * SB]);

    for (int kk = 0; kk < 16; kk++) {
        const int kg = kk * 16;  // batch index base
        {   // stage A: 128 x 16
            const int r = t >> 1, p = t & 1;
            *reinterpret_cast<uint4*>(&As[r * SA + p * 8]) =
                *reinterpret_cast<const uint4*>(&g_XhT[(size_t)(m0 + r) * BB + kg + p * 8]);
        }
        if (t < 160) {  // stage B: 16 x 80 from Vh
            const int kr = t / 10, n8 = (t % 10) * 8;
            *reinterpret_cast<uint4*>(&Bs[kr * SB + n8]) =
                *reinterpret_cast<const uint4*>(&g_Vh[(kg + kr) * DU + n0 + n8]);
        }
        __syncthreads();
        uint32_t a0, a1, a2, a3;
        ldsm_x4(a0, a1, a2, a3, aaddr);
#pragma unroll
        for (int nt = 0; nt < 10; nt++) {
            uint32_t b0, b1;
            ldsm_x2t(b0, b1, baddr0 + nt * 16);
            mma16816(acc[nt][0], acc[nt][1], acc[nt][2], acc[nt][3],
                     a0, a1, a2, a3, b0, b1);
        }
        __syncthreads();
    }
    // fused epilogue: multiply by Wt, reduce over (i,u)
    const int rg = lane >> 2, cb = (lane & 3) * 2;
    const int row0 = m0 + w * 16 + rg;
    float part[2][5];
#pragma unroll
    for (int cl = 0; cl < 2; cl++)
#pragma unroll
        for (int dl = 0; dl < 5; dl++) part[cl][dl] = 0.0f;
#pragma unroll
    for (int nt = 0; nt < 10; nt++) {
        const int dl = nt >> 1;
        const int col = n0 + nt * 8 + cb;
        const float2 f0 = __half22float2(
            *reinterpret_cast<const __half2*>(&g_Wt[(size_t)row0 * DU + col]));
        const float2 f1 = __half22float2(
            *reinterpret_cast<const __half2*>(&g_Wt[(size_t)(row0 + 8) * DU + col]));
        part[0][dl] += f0.x * acc[nt][0] + f0.y * acc[nt][1];
        part[1][dl] += f1.x * acc[nt][2] + f1.y * acc[nt][3];
    }
#pragma unroll
    for (int cl = 0; cl < 2; cl++)
#pragma unroll
        for (int dl = 0; dl < 5; dl++) {
            float v = part[cl][dl];
#pragma unroll
            for (int off = 16; off > 0; off >>= 1)
                v += __shfl_xor_sync(0xffffffffu, v, off);
            if (lane == 0) {
                const int c = (m0 + w * 16) / 8 + cl;
                const int d = nb * 5 + dl;
                g_Bij[c * NU + d] += v * (1.0f / 256.0f);
            }
        }
}

// ---------------------------------------------------------------------------
extern "C" void kernel_launch(void* const* d_in, const int* in_sizes, int n_in,
                              void* d_out, int out_size) {
    const float* x;
    const float* W;
    if (in_sizes[0] == BB * IU * IC) {
        x = (const float*)d_in[0];
        W = (const float*)d_in[1];
    } else {
        W = (const float*)d_in[0];
        x = (const float*)d_in[1];
    }
    float* out = (float*)d_out;

    k_prep_xh<<<BB, 288>>>(x);
    k_prep_xt<<<dim3(KK / 64, BB / 64), 256>>>();
    k_prep_wt<<<IC, 160>>>(W);
    for (int it = 0; it < 3; it++) {
        k_softmax<<<NU, 128>>>();
        k_sgemm<<<dim3(KS, 4), 256>>>();
        k_squash<<<BB, 160>>>(out);
        if (it < 2) k_agree<<<dim3(72, 2), 256>>>();
    }
}